// round 6
// baseline (speedup 1.0000x reference)
#include <cuda_runtime.h>
#include <math.h>
#include <cstdint>

// Problem constants (fixed by the reference)
#define NE 16
#define NW 3
#define NB 64
#define NP 4096
#define BP (NB * NP)
#define HBP (BP / 2)      // 131072 float2 per (expert,proj) plane
#define HP (NP / 2)       // 2048
#define TILE 128          // float2 slots per block tile
#define NPLANE 96         // 32 Q + 32 K + 32 V planes
#define PLANE_TILE_BYTES (TILE * 8)            // 1024 B per plane tile
#define SMEM_BYTES (NPLANE * PLANE_TILE_BYTES) // 98304 B

__global__ void __launch_bounds__(256, 2)
cantor_attn_kernel(const float2* __restrict__ Qp,
                   const float2* __restrict__ Kp,
                   const float2* __restrict__ Vp,
                   const float*  __restrict__ betas,
                   const float*  __restrict__ temperature,
                   const int*    __restrict__ routes,
                   float2*       __restrict__ out)
{
    extern __shared__ float2 sm[];     // [NPLANE][TILE] float2
    __shared__ uint64_t mbar;
    __shared__ int   s_route[NE * NW];
    __shared__ float s_gate[NE * NW];
    __shared__ float s_inv;

    const int t = threadIdx.x;
    const int tileBase = blockIdx.x * TILE;    // base idx2 of this block's tile

    const uint32_t mbar_addr = (uint32_t)__cvta_generic_to_shared(&mbar);

    if (t == 0) {
        asm volatile("mbarrier.init.shared.b64 [%0], 1;" :: "r"(mbar_addr) : "memory");
    }
    // tiny param staging (routes / gates / scale)
    if (t < NE * NW) {
        const int e = t / NW;
        const int r = routes[t];
        s_route[t] = r;
        s_gate[t]  = (r != e) ? __fdividef(1.0f, 1.0f + __expf(-betas[t])) : 1.0f;
    }
    if (t == NE * NW) {
        s_inv = __fdividef(1.0f, sqrtf(128.0f) * fabsf(temperature[0]));
    }
    __syncthreads();   // mbarrier.init + params visible to all

    if (t == 0) {
        asm volatile("mbarrier.arrive.expect_tx.shared.b64 _, [%0], %1;"
                     :: "r"(mbar_addr), "r"((uint32_t)SMEM_BYTES) : "memory");
    }
    __syncthreads();   // expect_tx set before any copy can complete

    // 96 bulk copies: one 1KB contiguous plane-tile each, issued by threads 0..95
    if (t < NPLANE) {
        const float2* src;
        if (t < 32)      src = Qp + (long)t        * HBP + tileBase;
        else if (t < 64) src = Kp + (long)(t - 32) * HBP + tileBase;
        else             src = Vp + (long)(t - 64) * HBP + tileBase;
        const uint32_t dst = (uint32_t)__cvta_generic_to_shared(sm + t * TILE);
        asm volatile(
            "cp.async.bulk.shared::cta.global.mbarrier::complete_tx::bytes [%0], [%1], %2, [%3];"
            :: "r"(dst), "l"(src), "r"((uint32_t)PLANE_TILE_BYTES), "r"(mbar_addr)
            : "memory");
    }

    // Wait for all SMEM_BYTES (phase 0) — canonical try_wait with suspend hint.
    {
        uint32_t done;
        asm volatile(
            "{\n\t"
            ".reg .pred p;\n\t"
            "mbarrier.try_wait.parity.acquire.cta.shared::cta.b64 p, [%1], %2;\n\t"
            "selp.b32 %0, 1, 0, p;\n\t"
            "}"
            : "=r"(done) : "r"(mbar_addr), "r"(0u) : "memory");
        if (!done) {
            asm volatile(
                "{\n\t"
                ".reg .pred P1;\n\t"
                "WAIT_LOOP_%=:\n\t"
                "mbarrier.try_wait.parity.acquire.cta.shared::cta.b64 P1, [%0], %1, 0x989680;\n\t"
                "@P1 bra.uni WAIT_DONE_%=;\n\t"
                "bra.uni WAIT_LOOP_%=;\n\t"
                "WAIT_DONE_%=:\n\t"
                "}"
                :: "r"(mbar_addr), "r"(0u) : "memory");
        }
    }

    // Compute: 256 threads = 128 slots x 2 expert-halves (8 experts each)
    const int s    = t & (TILE - 1);
    const int half = t >> 7;
    const int idx2 = tileBase + s;
    const int b    = idx2 >> 11;           // / HP
    const int p2   = idx2 & (HP - 1);
    const float inv = s_inv;
    const long obase = (long)b * (NE * HP) + p2;

    #pragma unroll
    for (int k = 0; k < NE / 2; k++) {
        const int e  = half * (NE / 2) + k;
        const int r0 = s_route[e * NW + 0];
        const int r1 = s_route[e * NW + 1];
        const int r2 = s_route[e * NW + 2];
        const float g0 = s_gate[e * NW + 0];
        const float g1 = s_gate[e * NW + 1];
        const float g2 = s_gate[e * NW + 2];

        const float2 qa  = sm[(2 * e)      * TILE + s];
        const float2 qb  = sm[(2 * e + 1)  * TILE + s];
        const float2 k0a = sm[(32 + 2 * r0)     * TILE + s];
        const float2 k0b = sm[(32 + 2 * r0 + 1) * TILE + s];
        const float2 k1a = sm[(32 + 2 * r1)     * TILE + s];
        const float2 k1b = sm[(32 + 2 * r1 + 1) * TILE + s];
        const float2 k2a = sm[(32 + 2 * r2)     * TILE + s];
        const float2 k2b = sm[(32 + 2 * r2 + 1) * TILE + s];
        const float2 v0a = sm[(64 + 2 * r0)     * TILE + s];
        const float2 v0b = sm[(64 + 2 * r0 + 1) * TILE + s];
        const float2 v1a = sm[(64 + 2 * r1)     * TILE + s];
        const float2 v1b = sm[(64 + 2 * r1 + 1) * TILE + s];
        const float2 v2a = sm[(64 + 2 * r2)     * TILE + s];
        const float2 v2b = sm[(64 + 2 * r2 + 1) * TILE + s];

        float2 res;

#define DO_LANE(c)                                                         \
        {                                                                  \
            const float q  = 0.5f * (qa.c + qb.c);                         \
            const float k0 = 0.5f * (k0a.c + k0b.c);                       \
            const float k1 = 0.5f * (k1a.c + k1b.c);                       \
            const float k2 = 0.5f * (k2a.c + k2b.c);                       \
            const float v0 = 0.5f * (v0a.c + v0b.c);                       \
            const float v1 = 0.5f * (v1a.c + v1b.c);                       \
            const float v2 = 0.5f * (v2a.c + v2b.c);                       \
            const float qi = q * inv;                                      \
            const float s0 = qi * k0 * g0;                                 \
            const float s1 = qi * k1 * g1;                                 \
            const float s2 = qi * k2 * g2;                                 \
            const float m  = fmaxf(fmaxf(s0, s1), s2);                     \
            const float x0 = __expf(s0 - m);                               \
            const float x1 = __expf(s1 - m);                               \
            const float x2 = __expf(s2 - m);                               \
            const float rs = __fdividef(1.0f, x0 + x1 + x2);               \
            res.c = (x0 * v0 + x1 * v1 + x2 * v2) * rs;                    \
        }

        DO_LANE(x)
        DO_LANE(y)
#undef DO_LANE

        out[obase + (long)e * HP] = res;
    }
}

extern "C" void kernel_launch(void* const* d_in, const int* in_sizes, int n_in,
                              void* d_out, int out_size)
{
    // metadata order: Q_proj, K_proj, V_proj, betas, temperature, routes, num_patches
    const float2* Qp    = (const float2*)d_in[0];
    const float2* Kp    = (const float2*)d_in[1];
    const float2* Vp    = (const float2*)d_in[2];
    const float*  betas = (const float*)d_in[3];
    const float*  temp  = (const float*)d_in[4];
    const int*    routes= (const int*)d_in[5];
    float2*       out   = (float2*)d_out;

    (void)in_sizes; (void)n_in; (void)out_size;

    static bool attr_set = false;
    if (!attr_set) {
        cudaFuncSetAttribute(cantor_attn_kernel,
                             cudaFuncAttributeMaxDynamicSharedMemorySize, SMEM_BYTES);
        attr_set = true;
    }

    const int threads = 256;
    const int blocks  = HBP / TILE;    // 1024
    cantor_attn_kernel<<<blocks, threads, SMEM_BYTES>>>(Qp, Kp, Vp, betas, temp, routes, out);
}